// round 1
// baseline (speedup 1.0000x reference)
#include <cuda_runtime.h>

// Problem constants
#define CB 2
#define CN 512
#define CA 14
#define CDIM 1024
#define CH 16
#define CD 64
#define CT (CB * CN * CA)        // 14336 tokens
#define CQKVN (3 * CDIM)         // 3072

// Scratch (device globals: allowed; no runtime allocation)
__device__ float g_qkv[(size_t)CT * CQKVN];   // [T, 3072]
__device__ float g_att[(size_t)CT * CDIM];    // [T, 1024]

// ---------------------------------------------------------------------------
// SGEMM with bias: C[M,N] = A[M,K] @ B[K,N] + bias[N]
// 128x128 block tile, BK=8, 8x8 per thread, 256 threads.
// Requires M%128==0, N%128==0, K%8==0 (true for all our shapes).
// ---------------------------------------------------------------------------
__global__ void __launch_bounds__(256) sgemm_bias(
    const float* __restrict__ A, const float* __restrict__ B,
    const float* __restrict__ bias, float* __restrict__ C,
    int M, int N, int K)
{
    __shared__ float As[8][128];   // transposed: As[k][m]
    __shared__ float Bs[8][128];   // Bs[k][n]

    const int tid  = threadIdx.x;
    const int brow = blockIdx.y << 7;
    const int bcol = blockIdx.x << 7;

    const int arow = tid >> 1;           // 0..127
    const int acol = (tid & 1) << 2;     // 0 or 4
    const int brw  = tid >> 5;           // 0..7
    const int bcl  = (tid & 31) << 2;    // 0..124

    const int ty = tid >> 4;             // 0..15
    const int tx = tid & 15;             // 0..15

    const float* Aptr = A + (size_t)(brow + arow) * K + acol;
    const float* Bptr = B + (size_t)brw * N + bcol + bcl;

    float acc[8][8];
#pragma unroll
    for (int i = 0; i < 8; i++)
#pragma unroll
        for (int j = 0; j < 8; j++) acc[i][j] = 0.f;

    for (int k0 = 0; k0 < K; k0 += 8) {
        float4 av = *(const float4*)(Aptr + k0);
        float4 bv = *(const float4*)(Bptr + (size_t)k0 * N);
        As[acol + 0][arow] = av.x;
        As[acol + 1][arow] = av.y;
        As[acol + 2][arow] = av.z;
        As[acol + 3][arow] = av.w;
        *(float4*)&Bs[brw][bcl] = bv;
        __syncthreads();

#pragma unroll
        for (int kk = 0; kk < 8; kk++) {
            float a[8], b[8];
            *(float4*)&a[0] = *(const float4*)&As[kk][ty * 8];
            *(float4*)&a[4] = *(const float4*)&As[kk][ty * 8 + 4];
            *(float4*)&b[0] = *(const float4*)&Bs[kk][tx * 8];
            *(float4*)&b[4] = *(const float4*)&Bs[kk][tx * 8 + 4];
#pragma unroll
            for (int i = 0; i < 8; i++)
#pragma unroll
                for (int j = 0; j < 8; j++)
                    acc[i][j] = fmaf(a[i], b[j], acc[i][j]);
        }
        __syncthreads();
    }

#pragma unroll
    for (int i = 0; i < 8; i++) {
        size_t crow = (size_t)(brow + ty * 8 + i) * N + bcol + tx * 8;
#pragma unroll
        for (int j = 0; j < 8; j += 4) {
            float4 o;
            o.x = acc[i][j + 0] + bias[bcol + tx * 8 + j + 0];
            o.y = acc[i][j + 1] + bias[bcol + tx * 8 + j + 1];
            o.z = acc[i][j + 2] + bias[bcol + tx * 8 + j + 2];
            o.w = acc[i][j + 3] + bias[bcol + tx * 8 + j + 3];
            *(float4*)(C + crow + j) = o;
        }
    }
}

// ---------------------------------------------------------------------------
// Attention: per block = one (b, atom r, head h, 64-row i-tile).
// Full 512-key score row-block kept in SMEM (64 x 513, pad => conflict-free
// softmax scan). Exact softmax, then O = P @ V, write [t, h*64+d].
// token t(b,i,r) = (b*512 + i)*14 + r ; per-token qkv row: h*192 + {0,64,128}+d
// ---------------------------------------------------------------------------
#define ATT_SS_LD 513
#define ATT_QK_LD 65
#define ATT_SMEM_FLOATS (64 * ATT_SS_LD + 2 * 64 * ATT_QK_LD + 4 * 64 + 64 + 64)
#define ATT_SMEM_BYTES (ATT_SMEM_FLOATS * 4)

__global__ void __launch_bounds__(256) attn_kernel(
    const float* __restrict__ qkv, float* __restrict__ out)
{
    extern __shared__ float sm[];
    float* sS   = sm;                       // 64 x 513 scores
    float* sQ   = sS + 64 * ATT_SS_LD;      // 64 x 65
    float* sKV  = sQ + 64 * ATT_QK_LD;      // 64 x 65 (K then V tiles)
    float* sred = sKV + 64 * ATT_QK_LD;     // 4 x 64 partial reductions
    float* srow = sred + 256;               // 64 row maxima
    float* srl  = srow + 64;                // 64 reciprocal row sums

    const int tid   = threadIdx.x;
    const int itile = blockIdx.x;           // 0..7  (64 q rows each)
    const int h     = blockIdx.y;           // 0..15
    const int bz    = blockIdx.z;           // 0..27
    const int b     = bz / CA;
    const int r     = bz % CA;
    const int qbase = h * 192;

    // ---- load Q tile (rows itile*64 .. +63) ----
    for (int idx = tid; idx < 64 * 16; idx += 256) {
        int i  = idx >> 4;
        int c4 = (idx & 15) << 2;
        size_t t = (size_t)(b * CN + itile * 64 + i) * CA + r;
        float4 v = *(const float4*)(qkv + t * CQKVN + qbase + c4);
        sQ[i * ATT_QK_LD + c4 + 0] = v.x;
        sQ[i * ATT_QK_LD + c4 + 1] = v.y;
        sQ[i * ATT_QK_LD + c4 + 2] = v.z;
        sQ[i * ATT_QK_LD + c4 + 3] = v.w;
    }

    const int ty = tid >> 4, tx = tid & 15;
    const int i0 = ty * 4, j0 = tx * 4;

    // ---- phase 1: S = (Q K^T) / 8, 8 key tiles of 64 ----
    for (int jt = 0; jt < 8; jt++) {
        __syncthreads();
        for (int idx = tid; idx < 64 * 16; idx += 256) {
            int j  = idx >> 4;
            int c4 = (idx & 15) << 2;
            size_t t = (size_t)(b * CN + jt * 64 + j) * CA + r;
            float4 v = *(const float4*)(qkv + t * CQKVN + qbase + 64 + c4);
            sKV[j * ATT_QK_LD + c4 + 0] = v.x;
            sKV[j * ATT_QK_LD + c4 + 1] = v.y;
            sKV[j * ATT_QK_LD + c4 + 2] = v.z;
            sKV[j * ATT_QK_LD + c4 + 3] = v.w;
        }
        __syncthreads();

        float acc[4][4];
#pragma unroll
        for (int u = 0; u < 4; u++)
#pragma unroll
            for (int v = 0; v < 4; v++) acc[u][v] = 0.f;

#pragma unroll 8
        for (int d = 0; d < 64; d++) {
            float a[4], bb[4];
#pragma unroll
            for (int u = 0; u < 4; u++) a[u]  = sQ[(i0 + u) * ATT_QK_LD + d];
#pragma unroll
            for (int v = 0; v < 4; v++) bb[v] = sKV[(j0 + v) * ATT_QK_LD + d];
#pragma unroll
            for (int u = 0; u < 4; u++)
#pragma unroll
                for (int v = 0; v < 4; v++)
                    acc[u][v] = fmaf(a[u], bb[v], acc[u][v]);
        }
#pragma unroll
        for (int u = 0; u < 4; u++)
#pragma unroll
            for (int v = 0; v < 4; v++)
                sS[(i0 + u) * ATT_SS_LD + jt * 64 + j0 + v] = acc[u][v] * 0.125f;
    }
    __syncthreads();

    // ---- phase 2: softmax over j (rows split across 4 thread-slices) ----
    {
        const int si = tid & 63;
        const int sl = tid >> 6;
        const int jb = sl * 128;
        float m = -1e30f;
        for (int j = jb; j < jb + 128; j++)
            m = fmaxf(m, sS[si * ATT_SS_LD + j]);
        sred[sl * 64 + si] = m;
        __syncthreads();
        if (sl == 0) {
            float mm = fmaxf(fmaxf(sred[si], sred[64 + si]),
                             fmaxf(sred[128 + si], sred[192 + si]));
            srow[si] = mm;
        }
        __syncthreads();
        m = srow[si];
        float l = 0.f;
        for (int j = jb; j < jb + 128; j++) {
            float e = __expf(sS[si * ATT_SS_LD + j] - m);
            sS[si * ATT_SS_LD + j] = e;
            l += e;
        }
        sred[sl * 64 + si] = l;
        __syncthreads();
        if (sl == 0)
            srl[si] = 1.f / (sred[si] + sred[64 + si] + sred[128 + si] + sred[192 + si]);
    }

    // ---- phase 3: O = P @ V ----
    const int d0 = tx * 4;
    float acc[4][4];
#pragma unroll
    for (int u = 0; u < 4; u++)
#pragma unroll
        for (int v = 0; v < 4; v++) acc[u][v] = 0.f;

    for (int jt = 0; jt < 8; jt++) {
        __syncthreads();
        for (int idx = tid; idx < 64 * 16; idx += 256) {
            int j  = idx >> 4;
            int c4 = (idx & 15) << 2;
            size_t t = (size_t)(b * CN + jt * 64 + j) * CA + r;
            float4 v = *(const float4*)(qkv + t * CQKVN + qbase + 128 + c4);
            sKV[j * ATT_QK_LD + c4 + 0] = v.x;
            sKV[j * ATT_QK_LD + c4 + 1] = v.y;
            sKV[j * ATT_QK_LD + c4 + 2] = v.z;
            sKV[j * ATT_QK_LD + c4 + 3] = v.w;
        }
        __syncthreads();

#pragma unroll 8
        for (int jj = 0; jj < 64; jj++) {
            float a[4], bb[4];
#pragma unroll
            for (int u = 0; u < 4; u++) a[u]  = sS[(i0 + u) * ATT_SS_LD + jt * 64 + jj];
#pragma unroll
            for (int v = 0; v < 4; v++) bb[v] = sKV[jj * ATT_QK_LD + d0 + v];
#pragma unroll
            for (int u = 0; u < 4; u++)
#pragma unroll
                for (int v = 0; v < 4; v++)
                    acc[u][v] = fmaf(a[u], bb[v], acc[u][v]);
        }
    }

#pragma unroll
    for (int u = 0; u < 4; u++) {
        float inv = srl[i0 + u];
        size_t t = (size_t)(b * CN + itile * 64 + i0 + u) * CA + r;
        float4 o;
        o.x = acc[u][0] * inv;
        o.y = acc[u][1] * inv;
        o.z = acc[u][2] * inv;
        o.w = acc[u][3] * inv;
        *(float4*)(out + t * CDIM + h * 64 + d0) = o;
    }
}

// ---------------------------------------------------------------------------
extern "C" void kernel_launch(void* const* d_in, const int* in_sizes, int n_in,
                              void* d_out, int out_size)
{
    const float* x      = (const float*)d_in[0];
    const float* w_qkv  = (const float*)d_in[1];
    const float* b_qkv  = (const float*)d_in[2];
    const float* w_proj = (const float*)d_in[3];
    const float* b_proj = (const float*)d_in[4];
    float* out = (float*)d_out;

    void *p0, *p1;
    cudaGetSymbolAddress(&p0, g_qkv);
    cudaGetSymbolAddress(&p1, g_att);
    float* qkv = (float*)p0;
    float* att = (float*)p1;

    cudaFuncSetAttribute(attn_kernel,
                         cudaFuncAttributeMaxDynamicSharedMemorySize,
                         ATT_SMEM_BYTES);

    // 1) QKV projection: [T,1024] @ [1024,3072] + b
    dim3 g1(CQKVN / 128, CT / 128);
    sgemm_bias<<<g1, 256>>>(x, w_qkv, b_qkv, qkv, CT, CQKVN, CDIM);

    // 2) attention per (b, atom, head, i-tile)
    dim3 g2(CN / 64, CH, CB * CA);
    attn_kernel<<<g2, 256, ATT_SMEM_BYTES>>>(qkv, att);

    // 3) output projection: [T,1024] @ [1024,1024] + b
    dim3 g3(CDIM / 128, CT / 128);
    sgemm_bias<<<g3, 256>>>(att, w_proj, b_proj, out, CT, CDIM, CDIM);
}

// round 4
// speedup vs baseline: 1.7510x; 1.7510x over previous
#include <cuda_runtime.h>
#include <cstdint>

// Problem constants
#define CB 2
#define CN 512
#define CA 14
#define CDIM 1024
#define CH 16
#define CD 64
#define CT (CB * CN * CA)        // 14336 tokens
#define CQKVN (3 * CDIM)         // 3072

// Scratch (device globals: allowed; no runtime allocation)
__device__ float g_qkv[(size_t)CT * CQKVN];    // [T, 3072]
__device__ float g_att[(size_t)CT * CDIM];     // [T, 1024] (tf32-rounded)
__device__ float g_xr [(size_t)CT * CDIM];     // x rounded to tf32
__device__ float g_bt1[(size_t)CQKVN * CDIM];  // w_qkv^T [3072,1024] tf32
__device__ float g_bt2[(size_t)CDIM * CDIM];   // w_proj^T [1024,1024] tf32

__device__ __forceinline__ float tf32r(float x) {
    uint32_t u;
    asm("cvt.rna.tf32.f32 %0, %1;" : "=r"(u) : "f"(x));
    return __uint_as_float(u);
}

__device__ __forceinline__ uint32_t smem_u32(const void* p) {
    uint32_t a;
    asm("{ .reg .u64 t; cvta.to.shared.u64 t, %1; cvt.u32.u64 %0, t; }"
        : "=r"(a) : "l"(p));
    return a;
}

__device__ __forceinline__ void cp_async16(uint32_t smem_addr, const void* gptr) {
    asm volatile("cp.async.ca.shared.global [%0], [%1], 16;"
                 :: "r"(smem_addr), "l"(gptr) : "memory");
}
__device__ __forceinline__ void cp_commit() {
    asm volatile("cp.async.commit_group;" ::: "memory");
}
__device__ __forceinline__ void cp_wait0() {
    asm volatile("cp.async.wait_group 0;" ::: "memory");
}

__device__ __forceinline__ void mma_tf32(
    float& c0, float& c1, float& c2, float& c3,
    uint32_t a0, uint32_t a1, uint32_t a2, uint32_t a3,
    uint32_t b0, uint32_t b1)
{
    asm volatile(
        "mma.sync.aligned.m16n8k8.row.col.f32.tf32.tf32.f32 "
        "{%0,%1,%2,%3}, {%4,%5,%6,%7}, {%8,%9}, {%0,%1,%2,%3};"
        : "+f"(c0), "+f"(c1), "+f"(c2), "+f"(c3)
        : "r"(a0), "r"(a1), "r"(a2), "r"(a3), "r"(b0), "r"(b1));
}

// ===========================================================================
// Pre-pass kernels
// ===========================================================================
__global__ void round_tf32_kernel(const float* __restrict__ in,
                                  float* __restrict__ out, int n4)
{
    int i = blockIdx.x * blockDim.x + threadIdx.x;
    if (i < n4) {
        float4 v = ((const float4*)in)[i];
        v.x = tf32r(v.x); v.y = tf32r(v.y); v.z = tf32r(v.z); v.w = tf32r(v.w);
        ((float4*)out)[i] = v;
    }
}

// in [K, N] row-major -> out [N, K] row-major, rounded to tf32
__global__ void transpose_round_kernel(const float* __restrict__ in,
                                       float* __restrict__ out, int K, int N)
{
    __shared__ float t[32][33];
    int n0 = blockIdx.x * 32, k0 = blockIdx.y * 32;
    for (int j = threadIdx.y; j < 32; j += 8)
        t[j][threadIdx.x] = in[(size_t)(k0 + j) * N + n0 + threadIdx.x];
    __syncthreads();
    for (int j = threadIdx.y; j < 32; j += 8)
        out[(size_t)(n0 + j) * K + k0 + threadIdx.x] = tf32r(t[threadIdx.x][j]);
}

// ===========================================================================
// tf32 mma.sync GEMM: C[M,N] = A[M,K] @ Bt[N,K]^T + bias
// 128x128 CTA tile, BK=32, 8 warps (2x4), warp tile 64x32, m16n8k8.
// A, Bt tf32-rounded fp32. 2-stage cp.async double buffer.
// ===========================================================================
#define GPAD 36
#define GTILE (128 * GPAD)                 // floats per (A or B) stage
#define GM_SMEM_BYTES (4 * GTILE * 4 * 2 / 2)   // 2 stages * 2 tensors * GTILE * 4B = 73728

__global__ void __launch_bounds__(256, 2) gemm_tf32mma(
    const float* __restrict__ A, const float* __restrict__ Bt,
    const float* __restrict__ bias, float* __restrict__ C,
    int N, int K)
{
    extern __shared__ float sm[];
    float* sA = sm;                 // [2][128][GPAD]
    float* sB = sm + 2 * GTILE;     // [2][128][GPAD]

    const int tid  = threadIdx.x;
    const int wid  = tid >> 5;
    const int lane = tid & 31;
    const int wm   = wid >> 2;          // 0..1
    const int wn   = wid & 3;           // 0..3
    const int r0   = lane >> 2;         // 0..7
    const int cc   = lane & 3;          // 0..3

    const int mBase = blockIdx.y * 128;
    const int nBase = blockIdx.x * 128;

    // gmem->smem mapping: 256 threads, each 4x float4 per tensor per tile
    const int lrow = tid >> 3;          // 0..31
    const int lcol = (tid & 7) << 2;    // 0,4,...,28

    const float* Ag = A  + (size_t)(mBase + lrow) * K + lcol;
    const float* Bg = Bt + (size_t)(nBase + lrow) * K + lcol;
    const uint32_t sAu = smem_u32(sA);
    const uint32_t sBu = smem_u32(sB);

    const int KIT = K >> 5;

    // prologue: load tile 0 -> stage 0
    {
#pragma unroll
        for (int p = 0; p < 4; p++) {
            int row = lrow + p * 32;
            cp_async16(sAu + (row * GPAD + lcol) * 4, Ag + (size_t)p * 32 * K);
            cp_async16(sBu + (row * GPAD + lcol) * 4, Bg + (size_t)p * 32 * K);
        }
        cp_commit();
    }

    float acc[4][4][4];
#pragma unroll
    for (int mt = 0; mt < 4; mt++)
#pragma unroll
        for (int nt = 0; nt < 4; nt++)
#pragma unroll
            for (int q = 0; q < 4; q++) acc[mt][nt][q] = 0.f;

    for (int kt = 0; kt < KIT; kt++) {
        cp_wait0();
        __syncthreads();

        const int s = kt & 1;
        // issue next tile load into other stage
        if (kt + 1 < KIT) {
            const int ns = (kt + 1) & 1;
            const size_t koff = (size_t)(kt + 1) * 32;
#pragma unroll
            for (int p = 0; p < 4; p++) {
                int row = lrow + p * 32;
                cp_async16(sAu + (ns * GTILE + row * GPAD + lcol) * 4,
                           Ag + (size_t)p * 32 * K + koff);
                cp_async16(sBu + (ns * GTILE + row * GPAD + lcol) * 4,
                           Bg + (size_t)p * 32 * K + koff);
            }
            cp_commit();
        }

        const float* pA = sA + s * GTILE;
        const float* pB = sB + s * GTILE;

#pragma unroll
        for (int ks = 0; ks < 4; ks++) {
            const int kc = ks * 8 + cc;
            uint32_t af[4][4], bf[4][2];
#pragma unroll
            for (int mt = 0; mt < 4; mt++) {
                const int row = wm * 64 + mt * 16 + r0;
                af[mt][0] = __float_as_uint(pA[row * GPAD + kc]);
                af[mt][1] = __float_as_uint(pA[(row + 8) * GPAD + kc]);
                af[mt][2] = __float_as_uint(pA[row * GPAD + kc + 4]);
                af[mt][3] = __float_as_uint(pA[(row + 8) * GPAD + kc + 4]);
            }
#pragma unroll
            for (int nt = 0; nt < 4; nt++) {
                const int col = wn * 32 + nt * 8 + r0;
                bf[nt][0] = __float_as_uint(pB[col * GPAD + kc]);
                bf[nt][1] = __float_as_uint(pB[col * GPAD + kc + 4]);
            }
#pragma unroll
            for (int mt = 0; mt < 4; mt++)
#pragma unroll
                for (int nt = 0; nt < 4; nt++)
                    mma_tf32(acc[mt][nt][0], acc[mt][nt][1],
                             acc[mt][nt][2], acc[mt][nt][3],
                             af[mt][0], af[mt][1], af[mt][2], af[mt][3],
                             bf[nt][0], bf[nt][1]);
        }
        __syncthreads();
    }

    // epilogue: direct gmem stores with bias
#pragma unroll
    for (int mt = 0; mt < 4; mt++) {
#pragma unroll
        for (int nt = 0; nt < 4; nt++) {
            const int row = mBase + wm * 64 + mt * 16 + r0;
            const int col = nBase + wn * 32 + nt * 8 + 2 * cc;
            const float b0 = __ldg(bias + col);
            const float b1 = __ldg(bias + col + 1);
            float2 v0 = make_float2(acc[mt][nt][0] + b0, acc[mt][nt][1] + b1);
            float2 v1 = make_float2(acc[mt][nt][2] + b0, acc[mt][nt][3] + b1);
            *(float2*)(C + (size_t)row * N + col)       = v0;
            *(float2*)(C + (size_t)(row + 8) * N + col) = v1;
        }
    }
}

// ===========================================================================
// Attention (fp32 FFMA; output rounded to tf32 for GEMM2)
// ===========================================================================
#define ATT_SS_LD 513
#define ATT_QK_LD 65
#define ATT_SMEM_FLOATS (64 * ATT_SS_LD + 2 * 64 * ATT_QK_LD + 4 * 64 + 64 + 64)
#define ATT_SMEM_BYTES (ATT_SMEM_FLOATS * 4)

__global__ void __launch_bounds__(256) attn_kernel(
    const float* __restrict__ qkv, float* __restrict__ out)
{
    extern __shared__ float smf[];
    float* sS   = smf;
    float* sQ   = sS + 64 * ATT_SS_LD;
    float* sKV  = sQ + 64 * ATT_QK_LD;
    float* sred = sKV + 64 * ATT_QK_LD;
    float* srow = sred + 256;
    float* srl  = srow + 64;

    const int tid   = threadIdx.x;
    const int itile = blockIdx.x;
    const int h     = blockIdx.y;
    const int bz    = blockIdx.z;
    const int b     = bz / CA;
    const int r     = bz % CA;
    const int qbase = h * 192;

    for (int idx = tid; idx < 64 * 16; idx += 256) {
        int i  = idx >> 4;
        int c4 = (idx & 15) << 2;
        size_t t = (size_t)(b * CN + itile * 64 + i) * CA + r;
        float4 v = *(const float4*)(qkv + t * CQKVN + qbase + c4);
        sQ[i * ATT_QK_LD + c4 + 0] = v.x;
        sQ[i * ATT_QK_LD + c4 + 1] = v.y;
        sQ[i * ATT_QK_LD + c4 + 2] = v.z;
        sQ[i * ATT_QK_LD + c4 + 3] = v.w;
    }

    const int ty = tid >> 4, tx = tid & 15;
    const int i0 = ty * 4, j0 = tx * 4;

    for (int jt = 0; jt < 8; jt++) {
        __syncthreads();
        for (int idx = tid; idx < 64 * 16; idx += 256) {
            int j  = idx >> 4;
            int c4 = (idx & 15) << 2;
            size_t t = (size_t)(b * CN + jt * 64 + j) * CA + r;
            float4 v = *(const float4*)(qkv + t * CQKVN + qbase + 64 + c4);
            sKV[j * ATT_QK_LD + c4 + 0] = v.x;
            sKV[j * ATT_QK_LD + c4 + 1] = v.y;
            sKV[j * ATT_QK_LD + c4 + 2] = v.z;
            sKV[j * ATT_QK_LD + c4 + 3] = v.w;
        }
        __syncthreads();

        float acc[4][4];
#pragma unroll
        for (int u = 0; u < 4; u++)
#pragma unroll
            for (int v = 0; v < 4; v++) acc[u][v] = 0.f;

#pragma unroll 8
        for (int d = 0; d < 64; d++) {
            float a[4], bb[4];
#pragma unroll
            for (int u = 0; u < 4; u++) a[u]  = sQ[(i0 + u) * ATT_QK_LD + d];
#pragma unroll
            for (int v = 0; v < 4; v++) bb[v] = sKV[(j0 + v) * ATT_QK_LD + d];
#pragma unroll
            for (int u = 0; u < 4; u++)
#pragma unroll
                for (int v = 0; v < 4; v++)
                    acc[u][v] = fmaf(a[u], bb[v], acc[u][v]);
        }
#pragma unroll
        for (int u = 0; u < 4; u++)
#pragma unroll
            for (int v = 0; v < 4; v++)
                sS[(i0 + u) * ATT_SS_LD + jt * 64 + j0 + v] = acc[u][v] * 0.125f;
    }
    __syncthreads();

    {
        const int si = tid & 63;
        const int sl = tid >> 6;
        const int jb = sl * 128;
        float m = -1e30f;
        for (int j = jb; j < jb + 128; j++)
            m = fmaxf(m, sS[si * ATT_SS_LD + j]);
        sred[sl * 64 + si] = m;
        __syncthreads();
        if (sl == 0) {
            float mm = fmaxf(fmaxf(sred[si], sred[64 + si]),
                             fmaxf(sred[128 + si], sred[192 + si]));
            srow[si] = mm;
        }
        __syncthreads();
        m = srow[si];
        float l = 0.f;
        for (int j = jb; j < jb + 128; j++) {
            float e = __expf(sS[si * ATT_SS_LD + j] - m);
            sS[si * ATT_SS_LD + j] = e;
            l += e;
        }
        sred[sl * 64 + si] = l;
        __syncthreads();
        if (sl == 0)
            srl[si] = 1.f / (sred[si] + sred[64 + si] + sred[128 + si] + sred[192 + si]);
    }

    const int d0 = tx * 4;
    float acc[4][4];
#pragma unroll
    for (int u = 0; u < 4; u++)
#pragma unroll
        for (int v = 0; v < 4; v++) acc[u][v] = 0.f;

    for (int jt = 0; jt < 8; jt++) {
        __syncthreads();
        for (int idx = tid; idx < 64 * 16; idx += 256) {
            int j  = idx >> 4;
            int c4 = (idx & 15) << 2;
            size_t t = (size_t)(b * CN + jt * 64 + j) * CA + r;
            float4 v = *(const float4*)(qkv + t * CQKVN + qbase + 128 + c4);
            sKV[j * ATT_QK_LD + c4 + 0] = v.x;
            sKV[j * ATT_QK_LD + c4 + 1] = v.y;
            sKV[j * ATT_QK_LD + c4 + 2] = v.z;
            sKV[j * ATT_QK_LD + c4 + 3] = v.w;
        }
        __syncthreads();

#pragma unroll 8
        for (int jj = 0; jj < 64; jj++) {
            float a[4], bb[4];
#pragma unroll
            for (int u = 0; u < 4; u++) a[u]  = sS[(i0 + u) * ATT_SS_LD + jt * 64 + jj];
#pragma unroll
            for (int v = 0; v < 4; v++) bb[v] = sKV[jj * ATT_QK_LD + d0 + v];
#pragma unroll
            for (int u = 0; u < 4; u++)
#pragma unroll
                for (int v = 0; v < 4; v++)
                    acc[u][v] = fmaf(a[u], bb[v], acc[u][v]);
        }
    }

#pragma unroll
    for (int u = 0; u < 4; u++) {
        float inv = srl[i0 + u];
        size_t t = (size_t)(b * CN + itile * 64 + i0 + u) * CA + r;
        float4 o;
        o.x = tf32r(acc[u][0] * inv);
        o.y = tf32r(acc[u][1] * inv);
        o.z = tf32r(acc[u][2] * inv);
        o.w = tf32r(acc[u][3] * inv);
        *(float4*)(out + t * CDIM + h * 64 + d0) = o;
    }
}

// ===========================================================================
// Host side
// ===========================================================================
extern "C" void kernel_launch(void* const* d_in, const int* in_sizes, int n_in,
                              void* d_out, int out_size)
{
    const float* x      = (const float*)d_in[0];
    const float* w_qkv  = (const float*)d_in[1];
    const float* b_qkv  = (const float*)d_in[2];
    const float* w_proj = (const float*)d_in[3];
    const float* b_proj = (const float*)d_in[4];
    float* out = (float*)d_out;

    void *p0, *p1, *p2, *p3, *p4;
    cudaGetSymbolAddress(&p0, g_qkv);
    cudaGetSymbolAddress(&p1, g_att);
    cudaGetSymbolAddress(&p2, g_xr);
    cudaGetSymbolAddress(&p3, g_bt1);
    cudaGetSymbolAddress(&p4, g_bt2);
    float* qkv = (float*)p0;
    float* att = (float*)p1;
    float* xr  = (float*)p2;
    float* bt1 = (float*)p3;
    float* bt2 = (float*)p4;

    cudaFuncSetAttribute(attn_kernel,
                         cudaFuncAttributeMaxDynamicSharedMemorySize, ATT_SMEM_BYTES);
    cudaFuncSetAttribute(gemm_tf32mma,
                         cudaFuncAttributeMaxDynamicSharedMemorySize, GM_SMEM_BYTES);

    // 0) pre-passes: round x, transpose+round weights
    {
        int n4 = CT * CDIM / 4;
        round_tf32_kernel<<<(n4 + 255) / 256, 256>>>(x, xr, n4);
        dim3 tb(32, 8);
        transpose_round_kernel<<<dim3(CQKVN / 32, CDIM / 32), tb>>>(w_qkv, bt1, CDIM, CQKVN);
        transpose_round_kernel<<<dim3(CDIM / 32, CDIM / 32), tb>>>(w_proj, bt2, CDIM, CDIM);
    }

    // 1) QKV projection: [T,1024] @ [1024,3072] + b
    gemm_tf32mma<<<dim3(CQKVN / 128, CT / 128), 256, GM_SMEM_BYTES>>>(
        xr, bt1, b_qkv, qkv, CQKVN, CDIM);

    // 2) attention
    attn_kernel<<<dim3(CN / 64, CH, CB * CA), 256, ATT_SMEM_BYTES>>>(qkv, att);

    // 3) output projection: [T,1024] @ [1024,1024] + b
    gemm_tf32mma<<<dim3(CDIM / 128, CT / 128), 256, GM_SMEM_BYTES>>>(
        att, bt2, b_proj, out, CDIM, CDIM);
}

// round 5
// speedup vs baseline: 2.1525x; 1.2293x over previous
#include <cuda_runtime.h>
#include <cstdint>

// Problem constants
#define CB 2
#define CN 512
#define CA 14
#define CDIM 1024
#define CH 16
#define CD 64
#define CT (CB * CN * CA)        // 14336 tokens
#define CQKVN (3 * CDIM)         // 3072

// Scratch (device globals: allowed; no runtime allocation)
__device__ float g_qkv[(size_t)CT * CQKVN];    // [T, 3072]
__device__ float g_att[(size_t)CT * CDIM];     // [T, 1024] (tf32-rounded)
__device__ float g_xr [(size_t)CT * CDIM];     // x rounded to tf32
__device__ float g_bt1[(size_t)CQKVN * CDIM];  // w_qkv^T [3072,1024] tf32
__device__ float g_bt2[(size_t)CDIM * CDIM];   // w_proj^T [1024,1024] tf32

__device__ __forceinline__ float tf32r(float x) {
    uint32_t u;
    asm("cvt.rna.tf32.f32 %0, %1;" : "=r"(u) : "f"(x));
    return __uint_as_float(u);
}

__device__ __forceinline__ uint32_t smem_u32(const void* p) {
    uint32_t a;
    asm("{ .reg .u64 t; cvta.to.shared.u64 t, %1; cvt.u32.u64 %0, t; }"
        : "=r"(a) : "l"(p));
    return a;
}

__device__ __forceinline__ void cp_async16(uint32_t smem_addr, const void* gptr) {
    asm volatile("cp.async.ca.shared.global [%0], [%1], 16;"
                 :: "r"(smem_addr), "l"(gptr) : "memory");
}
__device__ __forceinline__ void cp_commit() {
    asm volatile("cp.async.commit_group;" ::: "memory");
}
__device__ __forceinline__ void cp_wait0() {
    asm volatile("cp.async.wait_group 0;" ::: "memory");
}

__device__ __forceinline__ void mma_tf32(
    float& c0, float& c1, float& c2, float& c3,
    uint32_t a0, uint32_t a1, uint32_t a2, uint32_t a3,
    uint32_t b0, uint32_t b1)
{
    asm volatile(
        "mma.sync.aligned.m16n8k8.row.col.f32.tf32.tf32.f32 "
        "{%0,%1,%2,%3}, {%4,%5,%6,%7}, {%8,%9}, {%0,%1,%2,%3};"
        : "+f"(c0), "+f"(c1), "+f"(c2), "+f"(c3)
        : "r"(a0), "r"(a1), "r"(a2), "r"(a3), "r"(b0), "r"(b1));
}

// ===========================================================================
// Pre-pass kernels
// ===========================================================================
__global__ void round_tf32_kernel(const float* __restrict__ in,
                                  float* __restrict__ out, int n4)
{
    int i = blockIdx.x * blockDim.x + threadIdx.x;
    if (i < n4) {
        float4 v = ((const float4*)in)[i];
        v.x = tf32r(v.x); v.y = tf32r(v.y); v.z = tf32r(v.z); v.w = tf32r(v.w);
        ((float4*)out)[i] = v;
    }
}

// in [K, N] row-major -> out [N, K] row-major, rounded to tf32
__global__ void transpose_round_kernel(const float* __restrict__ in,
                                       float* __restrict__ out, int K, int N)
{
    __shared__ float t[32][33];
    int n0 = blockIdx.x * 32, k0 = blockIdx.y * 32;
    for (int j = threadIdx.y; j < 32; j += 8)
        t[j][threadIdx.x] = in[(size_t)(k0 + j) * N + n0 + threadIdx.x];
    __syncthreads();
    for (int j = threadIdx.y; j < 32; j += 8)
        out[(size_t)(n0 + j) * K + k0 + threadIdx.x] = tf32r(t[threadIdx.x][j]);
}

// ===========================================================================
// tf32 mma.sync GEMM: C[M,N] = A[M,K] @ Bt[N,K]^T + bias (unchanged from R4)
// ===========================================================================
#define GPAD 36
#define GTILE (128 * GPAD)
#define GM_SMEM_BYTES (4 * GTILE * 4 * 2 / 2)   // 73728

__global__ void __launch_bounds__(256, 2) gemm_tf32mma(
    const float* __restrict__ A, const float* __restrict__ Bt,
    const float* __restrict__ bias, float* __restrict__ C,
    int N, int K)
{
    extern __shared__ float sm[];
    float* sA = sm;
    float* sB = sm + 2 * GTILE;

    const int tid  = threadIdx.x;
    const int wid  = tid >> 5;
    const int lane = tid & 31;
    const int wm   = wid >> 2;
    const int wn   = wid & 3;
    const int r0   = lane >> 2;
    const int cc   = lane & 3;

    const int mBase = blockIdx.y * 128;
    const int nBase = blockIdx.x * 128;

    const int lrow = tid >> 3;
    const int lcol = (tid & 7) << 2;

    const float* Ag = A  + (size_t)(mBase + lrow) * K + lcol;
    const float* Bg = Bt + (size_t)(nBase + lrow) * K + lcol;
    const uint32_t sAu = smem_u32(sA);
    const uint32_t sBu = smem_u32(sB);

    const int KIT = K >> 5;

    {
#pragma unroll
        for (int p = 0; p < 4; p++) {
            int row = lrow + p * 32;
            cp_async16(sAu + (row * GPAD + lcol) * 4, Ag + (size_t)p * 32 * K);
            cp_async16(sBu + (row * GPAD + lcol) * 4, Bg + (size_t)p * 32 * K);
        }
        cp_commit();
    }

    float acc[4][4][4];
#pragma unroll
    for (int mt = 0; mt < 4; mt++)
#pragma unroll
        for (int nt = 0; nt < 4; nt++)
#pragma unroll
            for (int q = 0; q < 4; q++) acc[mt][nt][q] = 0.f;

    for (int kt = 0; kt < KIT; kt++) {
        cp_wait0();
        __syncthreads();

        const int s = kt & 1;
        if (kt + 1 < KIT) {
            const int ns = (kt + 1) & 1;
            const size_t koff = (size_t)(kt + 1) * 32;
#pragma unroll
            for (int p = 0; p < 4; p++) {
                int row = lrow + p * 32;
                cp_async16(sAu + (ns * GTILE + row * GPAD + lcol) * 4,
                           Ag + (size_t)p * 32 * K + koff);
                cp_async16(sBu + (ns * GTILE + row * GPAD + lcol) * 4,
                           Bg + (size_t)p * 32 * K + koff);
            }
            cp_commit();
        }

        const float* pA = sA + s * GTILE;
        const float* pB = sB + s * GTILE;

#pragma unroll
        for (int ks = 0; ks < 4; ks++) {
            const int kc = ks * 8 + cc;
            uint32_t af[4][4], bf[4][2];
#pragma unroll
            for (int mt = 0; mt < 4; mt++) {
                const int row = wm * 64 + mt * 16 + r0;
                af[mt][0] = __float_as_uint(pA[row * GPAD + kc]);
                af[mt][1] = __float_as_uint(pA[(row + 8) * GPAD + kc]);
                af[mt][2] = __float_as_uint(pA[row * GPAD + kc + 4]);
                af[mt][3] = __float_as_uint(pA[(row + 8) * GPAD + kc + 4]);
            }
#pragma unroll
            for (int nt = 0; nt < 4; nt++) {
                const int col = wn * 32 + nt * 8 + r0;
                bf[nt][0] = __float_as_uint(pB[col * GPAD + kc]);
                bf[nt][1] = __float_as_uint(pB[col * GPAD + kc + 4]);
            }
#pragma unroll
            for (int mt = 0; mt < 4; mt++)
#pragma unroll
                for (int nt = 0; nt < 4; nt++)
                    mma_tf32(acc[mt][nt][0], acc[mt][nt][1],
                             acc[mt][nt][2], acc[mt][nt][3],
                             af[mt][0], af[mt][1], af[mt][2], af[mt][3],
                             bf[nt][0], bf[nt][1]);
        }
        __syncthreads();
    }

#pragma unroll
    for (int mt = 0; mt < 4; mt++) {
#pragma unroll
        for (int nt = 0; nt < 4; nt++) {
            const int row = mBase + wm * 64 + mt * 16 + r0;
            const int col = nBase + wn * 32 + nt * 8 + 2 * cc;
            const float b0 = __ldg(bias + col);
            const float b1 = __ldg(bias + col + 1);
            float2 v0 = make_float2(acc[mt][nt][0] + b0, acc[mt][nt][1] + b1);
            float2 v1 = make_float2(acc[mt][nt][2] + b0, acc[mt][nt][3] + b1);
            *(float2*)(C + (size_t)row * N + col)       = v0;
            *(float2*)(C + (size_t)(row + 8) * N + col) = v1;
        }
    }
}

// ===========================================================================
// Attention via m16n8k8 tf32 mma.
// Block = (b, atom r, head h, 64-row i-tile). 256 threads = 8 warps.
// Phase 1: S = (Q*0.125) @ K^T   (Q pre-scaled, scale exact power of 2)
// Phase 2: softmax rows (rotated scans, conflict-free at ld=516)
// Phase 3: O = P @ V, divide by row sum, write tf32-rounded.
// Leading dims: sS=516, sQ/sK=68 (=4 mod 32), sV=72 (=8 mod 32): all
// mma fragment LDS patterns conflict-free.
// ===========================================================================
#define ASS_LD 516
#define AQ_LD 68
#define AV_LD 72
#define ATT_SMEM_FLOATS (64 * ASS_LD + 64 * AQ_LD + 64 * AV_LD + 256 + 64 + 64)
#define ATT_SMEM_BYTES (ATT_SMEM_FLOATS * 4)   // 169472

__global__ void __launch_bounds__(256) attn_kernel(
    const float* __restrict__ qkv, float* __restrict__ out)
{
    extern __shared__ float smf[];
    float* sS   = smf;                      // 64 x 516
    float* sQ   = sS + 64 * ASS_LD;         // 64 x 68
    float* sKV  = sQ + 64 * AQ_LD;          // 64 x 72 (K ld=68 / V ld=72)
    float* sred = sKV + 64 * AV_LD;         // 4 x 64
    float* srow = sred + 256;               // 64
    float* srl  = srow + 64;                // 64

    const int tid   = threadIdx.x;
    const int wid   = tid >> 5;
    const int lane  = tid & 31;
    const int r0    = lane >> 2;            // 0..7
    const int cc    = lane & 3;             // 0..3
    const int wm    = wid >> 1;             // 0..3 (m: 16 rows each)
    const int wn    = wid & 1;              // 0..1 (n: 32 cols each)

    const int itile = blockIdx.x;
    const int h     = blockIdx.y;
    const int bz    = blockIdx.z;
    const int b     = bz / CA;
    const int r     = bz % CA;
    const int qbase = h * 192;

    // ---- load Q tile, scaled by 1/8 (exact) + tf32 round ----
    for (int idx = tid; idx < 64 * 16; idx += 256) {
        int i  = idx >> 4;
        int c4 = (idx & 15) << 2;
        size_t t = (size_t)(b * CN + itile * 64 + i) * CA + r;
        float4 v = *(const float4*)(qkv + t * CQKVN + qbase + c4);
        sQ[i * AQ_LD + c4 + 0] = tf32r(0.125f * v.x);
        sQ[i * AQ_LD + c4 + 1] = tf32r(0.125f * v.y);
        sQ[i * AQ_LD + c4 + 2] = tf32r(0.125f * v.z);
        sQ[i * AQ_LD + c4 + 3] = tf32r(0.125f * v.w);
    }

    // ---- phase 1: S = Qs @ K^T via mma ----
    for (int jt = 0; jt < 8; jt++) {
        __syncthreads();
        for (int idx = tid; idx < 64 * 16; idx += 256) {
            int j  = idx >> 4;
            int c4 = (idx & 15) << 2;
            size_t t = (size_t)(b * CN + jt * 64 + j) * CA + r;
            float4 v = *(const float4*)(qkv + t * CQKVN + qbase + 64 + c4);
            sKV[j * AQ_LD + c4 + 0] = tf32r(v.x);
            sKV[j * AQ_LD + c4 + 1] = tf32r(v.y);
            sKV[j * AQ_LD + c4 + 2] = tf32r(v.z);
            sKV[j * AQ_LD + c4 + 3] = tf32r(v.w);
        }
        __syncthreads();

        float acc[4][4];
#pragma unroll
        for (int nt = 0; nt < 4; nt++)
#pragma unroll
            for (int q = 0; q < 4; q++) acc[nt][q] = 0.f;

        const int arow = wm * 16 + r0;
#pragma unroll
        for (int ks = 0; ks < 8; ks++) {
            const int kc = ks * 8 + cc;
            uint32_t a0 = __float_as_uint(sQ[arow * AQ_LD + kc]);
            uint32_t a1 = __float_as_uint(sQ[(arow + 8) * AQ_LD + kc]);
            uint32_t a2 = __float_as_uint(sQ[arow * AQ_LD + kc + 4]);
            uint32_t a3 = __float_as_uint(sQ[(arow + 8) * AQ_LD + kc + 4]);
#pragma unroll
            for (int nt = 0; nt < 4; nt++) {
                const int col = wn * 32 + nt * 8 + r0;
                uint32_t b0 = __float_as_uint(sKV[col * AQ_LD + kc]);
                uint32_t b1 = __float_as_uint(sKV[col * AQ_LD + kc + 4]);
                mma_tf32(acc[nt][0], acc[nt][1], acc[nt][2], acc[nt][3],
                         a0, a1, a2, a3, b0, b1);
            }
        }
#pragma unroll
        for (int nt = 0; nt < 4; nt++) {
            int base = arow * ASS_LD + jt * 64 + wn * 32 + nt * 8 + 2 * cc;
            sS[base]     = acc[nt][0];
            sS[base + 1] = acc[nt][1];
            sS[base + 8 * ASS_LD]     = acc[nt][2];
            sS[base + 8 * ASS_LD + 1] = acc[nt][3];
        }
    }
    __syncthreads();

    // ---- phase 2: softmax (rotated scans: bank = si + t mod 32) ----
    {
        const int si  = tid & 63;
        const int sl  = tid >> 6;
        const int jb  = sl * 128;
        const int off = (29 * si) & 31;
        float m = -1e30f;
        for (int t = 0; t < 128; t++) {
            int j = jb + ((t + off) & 127);
            m = fmaxf(m, sS[si * ASS_LD + j]);
        }
        sred[sl * 64 + si] = m;
        __syncthreads();
        if (sl == 0) {
            float mm = fmaxf(fmaxf(sred[si], sred[64 + si]),
                             fmaxf(sred[128 + si], sred[192 + si]));
            srow[si] = mm;
        }
        __syncthreads();
        m = srow[si];
        float l = 0.f;
        for (int t = 0; t < 128; t++) {
            int j = jb + ((t + off) & 127);
            float e = tf32r(__expf(sS[si * ASS_LD + j] - m));
            sS[si * ASS_LD + j] = e;
            l += e;
        }
        sred[sl * 64 + si] = l;
        __syncthreads();
        if (sl == 0)
            srl[si] = 1.f / (sred[si] + sred[64 + si] + sred[128 + si] + sred[192 + si]);
    }

    // ---- phase 3: O = P @ V via mma ----
    float acc[4][4];
#pragma unroll
    for (int nt = 0; nt < 4; nt++)
#pragma unroll
        for (int q = 0; q < 4; q++) acc[nt][q] = 0.f;

    const int arow = wm * 16 + r0;
    for (int jt = 0; jt < 8; jt++) {
        __syncthreads();
        for (int idx = tid; idx < 64 * 16; idx += 256) {
            int j  = idx >> 4;
            int c4 = (idx & 15) << 2;
            size_t t = (size_t)(b * CN + jt * 64 + j) * CA + r;
            float4 v = *(const float4*)(qkv + t * CQKVN + qbase + 128 + c4);
            sKV[j * AV_LD + c4 + 0] = tf32r(v.x);
            sKV[j * AV_LD + c4 + 1] = tf32r(v.y);
            sKV[j * AV_LD + c4 + 2] = tf32r(v.z);
            sKV[j * AV_LD + c4 + 3] = tf32r(v.w);
        }
        __syncthreads();

#pragma unroll
        for (int ks = 0; ks < 8; ks++) {
            const int kb = ks * 8;
            const int pcol = jt * 64 + kb + cc;
            uint32_t a0 = __float_as_uint(sS[arow * ASS_LD + pcol]);
            uint32_t a1 = __float_as_uint(sS[(arow + 8) * ASS_LD + pcol]);
            uint32_t a2 = __float_as_uint(sS[arow * ASS_LD + pcol + 4]);
            uint32_t a3 = __float_as_uint(sS[(arow + 8) * ASS_LD + pcol + 4]);
#pragma unroll
            for (int nt = 0; nt < 4; nt++) {
                const int col = wn * 32 + nt * 8 + r0;
                uint32_t b0 = __float_as_uint(sKV[(kb + cc) * AV_LD + col]);
                uint32_t b1 = __float_as_uint(sKV[(kb + cc + 4) * AV_LD + col]);
                mma_tf32(acc[nt][0], acc[nt][1], acc[nt][2], acc[nt][3],
                         a0, a1, a2, a3, b0, b1);
            }
        }
    }

    // ---- write O / row-sum, tf32-rounded for GEMM2 ----
    {
        const float inv0 = srl[arow];
        const float inv1 = srl[arow + 8];
        size_t t0 = (size_t)(b * CN + itile * 64 + arow) * CA + r;
        size_t t1 = (size_t)(b * CN + itile * 64 + arow + 8) * CA + r;
#pragma unroll
        for (int nt = 0; nt < 4; nt++) {
            const int col = h * 64 + wn * 32 + nt * 8 + 2 * cc;
            float2 v0 = make_float2(tf32r(acc[nt][0] * inv0), tf32r(acc[nt][1] * inv0));
            float2 v1 = make_float2(tf32r(acc[nt][2] * inv1), tf32r(acc[nt][3] * inv1));
            *(float2*)(out + t0 * CDIM + col) = v0;
            *(float2*)(out + t1 * CDIM + col) = v1;
        }
    }
}

// ===========================================================================
// Host side
// ===========================================================================
extern "C" void kernel_launch(void* const* d_in, const int* in_sizes, int n_in,
                              void* d_out, int out_size)
{
    const float* x      = (const float*)d_in[0];
    const float* w_qkv  = (const float*)d_in[1];
    const float* b_qkv  = (const float*)d_in[2];
    const float* w_proj = (const float*)d_in[3];
    const float* b_proj = (const float*)d_in[4];
    float* out = (float*)d_out;

    void *p0, *p1, *p2, *p3, *p4;
    cudaGetSymbolAddress(&p0, g_qkv);
    cudaGetSymbolAddress(&p1, g_att);
    cudaGetSymbolAddress(&p2, g_xr);
    cudaGetSymbolAddress(&p3, g_bt1);
    cudaGetSymbolAddress(&p4, g_bt2);
    float* qkv = (float*)p0;
    float* att = (float*)p1;
    float* xr  = (float*)p2;
    float* bt1 = (float*)p3;
    float* bt2 = (float*)p4;

    cudaFuncSetAttribute(attn_kernel,
                         cudaFuncAttributeMaxDynamicSharedMemorySize, ATT_SMEM_BYTES);
    cudaFuncSetAttribute(gemm_tf32mma,
                         cudaFuncAttributeMaxDynamicSharedMemorySize, GM_SMEM_BYTES);

    // 0) pre-passes: round x, transpose+round weights
    {
        int n4 = CT * CDIM / 4;
        round_tf32_kernel<<<(n4 + 255) / 256, 256>>>(x, xr, n4);
        dim3 tb(32, 8);
        transpose_round_kernel<<<dim3(CQKVN / 32, CDIM / 32), tb>>>(w_qkv, bt1, CDIM, CQKVN);
        transpose_round_kernel<<<dim3(CDIM / 32, CDIM / 32), tb>>>(w_proj, bt2, CDIM, CDIM);
    }

    // 1) QKV projection: [T,1024] @ [1024,3072] + b
    gemm_tf32mma<<<dim3(CQKVN / 128, CT / 128), 256, GM_SMEM_BYTES>>>(
        xr, bt1, b_qkv, qkv, CQKVN, CDIM);

    // 2) attention (tensor-core)
    attn_kernel<<<dim3(CN / 64, CH, CB * CA), 256, ATT_SMEM_BYTES>>>(qkv, att);

    // 3) output projection: [T,1024] @ [1024,1024] + b
    gemm_tf32mma<<<dim3(CDIM / 128, CT / 128), 256, GM_SMEM_BYTES>>>(
        att, bt2, b_proj, out, CDIM, CDIM);
}

// round 8
// speedup vs baseline: 4.1106x; 1.9097x over previous
#include <cuda_runtime.h>
#include <cstdint>

// Problem constants
#define CB 2
#define CN 512
#define CA 14
#define CDIM 1024
#define CH 16
#define CD 64
#define CT (CB * CN * CA)        // 14336 tokens
#define CQKVN (3 * CDIM)         // 3072

// Scratch (device globals: allowed; no runtime allocation)
__device__ float g_qkv[(size_t)CT * CQKVN];    // [T, 3072]
__device__ float g_att[(size_t)CT * CDIM];     // [T, 1024] (tf32-rounded)
__device__ float g_xr [(size_t)CT * CDIM];     // x rounded to tf32
__device__ float g_bt1[(size_t)CQKVN * CDIM];  // w_qkv^T [3072,1024] tf32
__device__ float g_bt2[(size_t)CDIM * CDIM];   // w_proj^T [1024,1024] tf32

__device__ __forceinline__ float tf32r(float x) {
    uint32_t u;
    asm("cvt.rna.tf32.f32 %0, %1;" : "=r"(u) : "f"(x));
    return __uint_as_float(u);
}

__device__ __forceinline__ uint32_t smem_u32(const void* p) {
    uint32_t a;
    asm("{ .reg .u64 t; cvta.to.shared.u64 t, %1; cvt.u32.u64 %0, t; }"
        : "=r"(a) : "l"(p));
    return a;
}

__device__ __forceinline__ void cp_async16(uint32_t smem_addr, const void* gptr) {
    asm volatile("cp.async.ca.shared.global [%0], [%1], 16;"
                 :: "r"(smem_addr), "l"(gptr) : "memory");
}
__device__ __forceinline__ void cp_commit() {
    asm volatile("cp.async.commit_group;" ::: "memory");
}
__device__ __forceinline__ void cp_wait0() {
    asm volatile("cp.async.wait_group 0;" ::: "memory");
}

__device__ __forceinline__ void mma_tf32(
    float& c0, float& c1, float& c2, float& c3,
    uint32_t a0, uint32_t a1, uint32_t a2, uint32_t a3,
    uint32_t b0, uint32_t b1)
{
    asm volatile(
        "mma.sync.aligned.m16n8k8.row.col.f32.tf32.tf32.f32 "
        "{%0,%1,%2,%3}, {%4,%5,%6,%7}, {%8,%9}, {%0,%1,%2,%3};"
        : "+f"(c0), "+f"(c1), "+f"(c2), "+f"(c3)
        : "r"(a0), "r"(a1), "r"(a2), "r"(a3), "r"(b0), "r"(b1));
}

// ===========================================================================
// Pre-pass kernels
// ===========================================================================
__global__ void round_tf32_kernel(const float* __restrict__ in,
                                  float* __restrict__ out, int n4)
{
    int i = blockIdx.x * blockDim.x + threadIdx.x;
    if (i < n4) {
        float4 v = ((const float4*)in)[i];
        v.x = tf32r(v.x); v.y = tf32r(v.y); v.z = tf32r(v.z); v.w = tf32r(v.w);
        ((float4*)out)[i] = v;
    }
}

// in [K, N] row-major -> out [N, K] row-major, rounded to tf32
__global__ void transpose_round_kernel(const float* __restrict__ in,
                                       float* __restrict__ out, int K, int N)
{
    __shared__ float t[32][33];
    int n0 = blockIdx.x * 32, k0 = blockIdx.y * 32;
    for (int j = threadIdx.y; j < 32; j += 8)
        t[j][threadIdx.x] = in[(size_t)(k0 + j) * N + n0 + threadIdx.x];
    __syncthreads();
    for (int j = threadIdx.y; j < 32; j += 8)
        out[(size_t)(n0 + j) * K + k0 + threadIdx.x] = tf32r(t[threadIdx.x][j]);
}

// ===========================================================================
// tf32 mma.sync GEMM: C[M,N] = A[M,K] @ Bt[N,K]^T + bias  (EXACT R5 version)
// ===========================================================================
#define GPAD 36
#define GTILE (128 * GPAD)
#define GM_SMEM_BYTES (4 * GTILE * 4 * 2 / 2)   // 73728

__global__ void __launch_bounds__(256, 2) gemm_tf32mma(
    const float* __restrict__ A, const float* __restrict__ Bt,
    const float* __restrict__ bias, float* __restrict__ C,
    int N, int K)
{
    extern __shared__ float sm[];
    float* sA = sm;
    float* sB = sm + 2 * GTILE;

    const int tid  = threadIdx.x;
    const int wid  = tid >> 5;
    const int lane = tid & 31;
    const int wm   = wid >> 2;
    const int wn   = wid & 3;
    const int r0   = lane >> 2;
    const int cc   = lane & 3;

    const int mBase = blockIdx.y * 128;
    const int nBase = blockIdx.x * 128;

    const int lrow = tid >> 3;
    const int lcol = (tid & 7) << 2;

    const float* Ag = A  + (size_t)(mBase + lrow) * K + lcol;
    const float* Bg = Bt + (size_t)(nBase + lrow) * K + lcol;
    const uint32_t sAu = smem_u32(sA);
    const uint32_t sBu = smem_u32(sB);

    const int KIT = K >> 5;

    {
#pragma unroll
        for (int p = 0; p < 4; p++) {
            int row = lrow + p * 32;
            cp_async16(sAu + (row * GPAD + lcol) * 4, Ag + (size_t)p * 32 * K);
            cp_async16(sBu + (row * GPAD + lcol) * 4, Bg + (size_t)p * 32 * K);
        }
        cp_commit();
    }

    float acc[4][4][4];
#pragma unroll
    for (int mt = 0; mt < 4; mt++)
#pragma unroll
        for (int nt = 0; nt < 4; nt++)
#pragma unroll
            for (int q = 0; q < 4; q++) acc[mt][nt][q] = 0.f;

    for (int kt = 0; kt < KIT; kt++) {
        cp_wait0();
        __syncthreads();

        const int s = kt & 1;
        if (kt + 1 < KIT) {
            const int ns = (kt + 1) & 1;
            const size_t koff = (size_t)(kt + 1) * 32;
#pragma unroll
            for (int p = 0; p < 4; p++) {
                int row = lrow + p * 32;
                cp_async16(sAu + (ns * GTILE + row * GPAD + lcol) * 4,
                           Ag + (size_t)p * 32 * K + koff);
                cp_async16(sBu + (ns * GTILE + row * GPAD + lcol) * 4,
                           Bg + (size_t)p * 32 * K + koff);
            }
            cp_commit();
        }

        const float* pA = sA + s * GTILE;
        const float* pB = sB + s * GTILE;

#pragma unroll
        for (int ks = 0; ks < 4; ks++) {
            const int kc = ks * 8 + cc;
            uint32_t af[4][4], bf[4][2];
#pragma unroll
            for (int mt = 0; mt < 4; mt++) {
                const int row = wm * 64 + mt * 16 + r0;
                af[mt][0] = __float_as_uint(pA[row * GPAD + kc]);
                af[mt][1] = __float_as_uint(pA[(row + 8) * GPAD + kc]);
                af[mt][2] = __float_as_uint(pA[row * GPAD + kc + 4]);
                af[mt][3] = __float_as_uint(pA[(row + 8) * GPAD + kc + 4]);
            }
#pragma unroll
            for (int nt = 0; nt < 4; nt++) {
                const int col = wn * 32 + nt * 8 + r0;
                bf[nt][0] = __float_as_uint(pB[col * GPAD + kc]);
                bf[nt][1] = __float_as_uint(pB[col * GPAD + kc + 4]);
            }
#pragma unroll
            for (int mt = 0; mt < 4; mt++)
#pragma unroll
                for (int nt = 0; nt < 4; nt++)
                    mma_tf32(acc[mt][nt][0], acc[mt][nt][1],
                             acc[mt][nt][2], acc[mt][nt][3],
                             af[mt][0], af[mt][1], af[mt][2], af[mt][3],
                             bf[nt][0], bf[nt][1]);
        }
        __syncthreads();
    }

#pragma unroll
    for (int mt = 0; mt < 4; mt++) {
#pragma unroll
        for (int nt = 0; nt < 4; nt++) {
            const int row = mBase + wm * 64 + mt * 16 + r0;
            const int col = nBase + wn * 32 + nt * 8 + 2 * cc;
            const float b0 = __ldg(bias + col);
            const float b1 = __ldg(bias + col + 1);
            float2 v0 = make_float2(acc[mt][nt][0] + b0, acc[mt][nt][1] + b1);
            float2 v1 = make_float2(acc[mt][nt][2] + b0, acc[mt][nt][3] + b1);
            *(float2*)(C + (size_t)row * N + col)       = v0;
            *(float2*)(C + (size_t)(row + 8) * N + col) = v1;
        }
    }
}

// ===========================================================================
// Flash attention: register-resident S/P, online softmax, m16n8k8 tf32 mma.
// Block = (b, atom r, head h, 128-row i-tile); 8 warps x 16 rows.
// K/V tiles loaded with plain LDG + tf32r + STS, single-buffered (R5 style —
// NO cp.async, NO forced occupancy). Smem 69KB.
// ===========================================================================
#define AQ_LD 68
#define AK_LD 68
#define AV_LD 72
#define ATT_SMEM_FLOATS (128 * AQ_LD + 64 * AK_LD + 64 * AV_LD)
#define ATT_SMEM_BYTES (ATT_SMEM_FLOATS * 4)   // 70656

__global__ void __launch_bounds__(256) attn_kernel(
    const float* __restrict__ qkv, float* __restrict__ out)
{
    extern __shared__ float smf[];
    float* sQ = smf;                     // [128][AQ_LD]
    float* sK = sQ + 128 * AQ_LD;        // [64][AK_LD]
    float* sV = sK + 64 * AK_LD;         // [64][AV_LD]

    const int tid  = threadIdx.x;
    const int wid  = tid >> 5;
    const int lane = tid & 31;
    const int r0   = lane >> 2;          // 0..7
    const int cc   = lane & 3;           // 0..3

    const int itile = blockIdx.x;        // 0..3 (128 q-rows each)
    const int h     = blockIdx.y;
    const int bz    = blockIdx.z;
    const int b     = bz / CA;
    const int r     = bz % CA;
    const int qbase = h * 192;

    // ---- stage Q (scaled by 1/8, tf32-rounded) ----
    for (int idx = tid; idx < 128 * 16; idx += 256) {
        int i  = idx >> 4;
        int c4 = (idx & 15) << 2;
        size_t t = (size_t)(b * CN + itile * 128 + i) * CA + r;
        float4 v = *(const float4*)(qkv + t * CQKVN + qbase + c4);
        sQ[i * AQ_LD + c4 + 0] = tf32r(0.125f * v.x);
        sQ[i * AQ_LD + c4 + 1] = tf32r(0.125f * v.y);
        sQ[i * AQ_LD + c4 + 2] = tf32r(0.125f * v.z);
        sQ[i * AQ_LD + c4 + 3] = tf32r(0.125f * v.w);
    }

    const int arow = wid * 16 + r0;

    float m0 = -1e30f, m1 = -1e30f, l0 = 0.f, l1 = 0.f;
    float oacc[8][4];
#pragma unroll
    for (int nt = 0; nt < 8; nt++)
#pragma unroll
        for (int q = 0; q < 4; q++) oacc[nt][q] = 0.f;

    const int L1 = (lane & 28) | (cc >> 1);
    const int L2 = L1 + 2;
    const bool odd = cc & 1;

    for (int jt = 0; jt < 8; jt++) {
        __syncthreads();   // previous iteration's readers done (and Q staged at jt=0)

        // ---- load K/V tile jt (plain LDG -> tf32r -> STS, R5 style) ----
        for (int idx = tid; idx < 64 * 16; idx += 256) {
            int j  = idx >> 4;
            int c4 = (idx & 15) << 2;
            size_t t = (size_t)(b * CN + jt * 64 + j) * CA + r;
            const float* base = qkv + t * CQKVN + qbase;
            float4 kv = *(const float4*)(base + 64 + c4);
            sK[j * AK_LD + c4 + 0] = tf32r(kv.x);
            sK[j * AK_LD + c4 + 1] = tf32r(kv.y);
            sK[j * AK_LD + c4 + 2] = tf32r(kv.z);
            sK[j * AK_LD + c4 + 3] = tf32r(kv.w);
            float4 vv = *(const float4*)(base + 128 + c4);
            sV[j * AV_LD + c4 + 0] = tf32r(vv.x);
            sV[j * AV_LD + c4 + 1] = tf32r(vv.y);
            sV[j * AV_LD + c4 + 2] = tf32r(vv.z);
            sV[j * AV_LD + c4 + 3] = tf32r(vv.w);
        }
        __syncthreads();

        // ---- S = Qs @ K^T (16 x 64 per warp) ----
        float sacc[8][4];
#pragma unroll
        for (int nt = 0; nt < 8; nt++)
#pragma unroll
            for (int q = 0; q < 4; q++) sacc[nt][q] = 0.f;

#pragma unroll
        for (int ks = 0; ks < 8; ks++) {
            const int kc = ks * 8 + cc;
            uint32_t a0 = __float_as_uint(sQ[arow * AQ_LD + kc]);
            uint32_t a1 = __float_as_uint(sQ[(arow + 8) * AQ_LD + kc]);
            uint32_t a2 = __float_as_uint(sQ[arow * AQ_LD + kc + 4]);
            uint32_t a3 = __float_as_uint(sQ[(arow + 8) * AQ_LD + kc + 4]);
#pragma unroll
            for (int nt = 0; nt < 8; nt++) {
                const int col = nt * 8 + r0;
                uint32_t b0 = __float_as_uint(sK[col * AK_LD + kc]);
                uint32_t b1 = __float_as_uint(sK[col * AK_LD + kc + 4]);
                mma_tf32(sacc[nt][0], sacc[nt][1], sacc[nt][2], sacc[nt][3],
                         a0, a1, a2, a3, b0, b1);
            }
        }

        // ---- online softmax (rows r0 / r0+8; quads own disjoint columns) ----
        float mx0 = -1e30f, mx1 = -1e30f;
#pragma unroll
        for (int nt = 0; nt < 8; nt++) {
            mx0 = fmaxf(mx0, fmaxf(sacc[nt][0], sacc[nt][1]));
            mx1 = fmaxf(mx1, fmaxf(sacc[nt][2], sacc[nt][3]));
        }
        mx0 = fmaxf(mx0, __shfl_xor_sync(0xffffffffu, mx0, 1));
        mx0 = fmaxf(mx0, __shfl_xor_sync(0xffffffffu, mx0, 2));
        mx1 = fmaxf(mx1, __shfl_xor_sync(0xffffffffu, mx1, 1));
        mx1 = fmaxf(mx1, __shfl_xor_sync(0xffffffffu, mx1, 2));

        const float mn0 = fmaxf(m0, mx0);
        const float mn1 = fmaxf(m1, mx1);
        const float sc0 = __expf(m0 - mn0);
        const float sc1 = __expf(m1 - mn1);
        m0 = mn0; m1 = mn1;
        l0 *= sc0; l1 *= sc1;
#pragma unroll
        for (int nt = 0; nt < 8; nt++) {
            oacc[nt][0] *= sc0; oacc[nt][1] *= sc0;
            oacc[nt][2] *= sc1; oacc[nt][3] *= sc1;
        }
        float ps0 = 0.f, ps1 = 0.f;
#pragma unroll
        for (int nt = 0; nt < 8; nt++) {
            float p0 = tf32r(__expf(sacc[nt][0] - m0));
            float p1 = tf32r(__expf(sacc[nt][1] - m0));
            float p2 = tf32r(__expf(sacc[nt][2] - m1));
            float p3 = tf32r(__expf(sacc[nt][3] - m1));
            ps0 += p0 + p1; ps1 += p2 + p3;
            sacc[nt][0] = p0; sacc[nt][1] = p1;
            sacc[nt][2] = p2; sacc[nt][3] = p3;
        }
        l0 += ps0; l1 += ps1;   // per-lane partials; quad-reduced at end

        // ---- O += P @ V (C-fragment -> A-fragment via quad shuffles) ----
#pragma unroll
        for (int ks = 0; ks < 8; ks++) {
            float s0 = __shfl_sync(0xffffffffu, sacc[ks][0], L1);
            float s1 = __shfl_sync(0xffffffffu, sacc[ks][1], L1);
            float s2 = __shfl_sync(0xffffffffu, sacc[ks][2], L1);
            float s3 = __shfl_sync(0xffffffffu, sacc[ks][3], L1);
            float t0 = __shfl_sync(0xffffffffu, sacc[ks][0], L2);
            float t1 = __shfl_sync(0xffffffffu, sacc[ks][1], L2);
            float t2 = __shfl_sync(0xffffffffu, sacc[ks][2], L2);
            float t3 = __shfl_sync(0xffffffffu, sacc[ks][3], L2);
            uint32_t a0 = __float_as_uint(odd ? s1 : s0);
            uint32_t a1 = __float_as_uint(odd ? s3 : s2);
            uint32_t a2 = __float_as_uint(odd ? t1 : t0);
            uint32_t a3 = __float_as_uint(odd ? t3 : t2);
            const int kb = ks * 8;
#pragma unroll
            for (int nt = 0; nt < 8; nt++) {
                const int col = nt * 8 + r0;
                uint32_t b0 = __float_as_uint(sV[(kb + cc) * AV_LD + col]);
                uint32_t b1 = __float_as_uint(sV[(kb + cc + 4) * AV_LD + col]);
                mma_tf32(oacc[nt][0], oacc[nt][1], oacc[nt][2], oacc[nt][3],
                         a0, a1, a2, a3, b0, b1);
            }
        }
    }

    // ---- finalize: quad-reduce row sums, divide, write tf32-rounded ----
    l0 += __shfl_xor_sync(0xffffffffu, l0, 1);
    l0 += __shfl_xor_sync(0xffffffffu, l0, 2);
    l1 += __shfl_xor_sync(0xffffffffu, l1, 1);
    l1 += __shfl_xor_sync(0xffffffffu, l1, 2);
    const float inv0 = 1.f / l0;
    const float inv1 = 1.f / l1;

    const size_t t0 = (size_t)(b * CN + itile * 128 + arow) * CA + r;
    const size_t t1 = (size_t)(b * CN + itile * 128 + arow + 8) * CA + r;
#pragma unroll
    for (int nt = 0; nt < 8; nt++) {
        const int col = h * 64 + nt * 8 + 2 * cc;
        float2 v0 = make_float2(tf32r(oacc[nt][0] * inv0), tf32r(oacc[nt][1] * inv0));
        float2 v1 = make_float2(tf32r(oacc[nt][2] * inv1), tf32r(oacc[nt][3] * inv1));
        *(float2*)(out + t0 * CDIM + col) = v0;
        *(float2*)(out + t1 * CDIM + col) = v1;
    }
}

// ===========================================================================
// Host side
// ===========================================================================
extern "C" void kernel_launch(void* const* d_in, const int* in_sizes, int n_in,
                              void* d_out, int out_size)
{
    const float* x      = (const float*)d_in[0];
    const float* w_qkv  = (const float*)d_in[1];
    const float* b_qkv  = (const float*)d_in[2];
    const float* w_proj = (const float*)d_in[3];
    const float* b_proj = (const float*)d_in[4];
    float* out = (float*)d_out;

    void *p0, *p1, *p2, *p3, *p4;
    cudaGetSymbolAddress(&p0, g_qkv);
    cudaGetSymbolAddress(&p1, g_att);
    cudaGetSymbolAddress(&p2, g_xr);
    cudaGetSymbolAddress(&p3, g_bt1);
    cudaGetSymbolAddress(&p4, g_bt2);
    float* qkv = (float*)p0;
    float* att = (float*)p1;
    float* xr  = (float*)p2;
    float* bt1 = (float*)p3;
    float* bt2 = (float*)p4;

    cudaFuncSetAttribute(attn_kernel,
                         cudaFuncAttributeMaxDynamicSharedMemorySize, ATT_SMEM_BYTES);
    cudaFuncSetAttribute(gemm_tf32mma,
                         cudaFuncAttributeMaxDynamicSharedMemorySize, GM_SMEM_BYTES);

    // 0) pre-passes: round x, transpose+round weights
    {
        int n4 = CT * CDIM / 4;
        round_tf32_kernel<<<(n4 + 255) / 256, 256>>>(x, xr, n4);
        dim3 tb(32, 8);
        transpose_round_kernel<<<dim3(CQKVN / 32, CDIM / 32), tb>>>(w_qkv, bt1, CDIM, CQKVN);
        transpose_round_kernel<<<dim3(CDIM / 32, CDIM / 32), tb>>>(w_proj, bt2, CDIM, CDIM);
    }

    // 1) QKV projection: [T,1024] @ [1024,3072] + b
    gemm_tf32mma<<<dim3(CQKVN / 128, CT / 128), 256, GM_SMEM_BYTES>>>(
        xr, bt1, b_qkv, qkv, CQKVN, CDIM);

    // 2) flash attention (tensor-core, register-resident softmax)
    attn_kernel<<<dim3(CN / 128, CH, CB * CA), 256, ATT_SMEM_BYTES>>>(qkv, att);

    // 3) output projection: [T,1024] @ [1024,1024] + b
    gemm_tf32mma<<<dim3(CDIM / 128, CT / 128), 256, GM_SMEM_BYTES>>>(
        att, bt2, b_proj, out, CDIM, CDIM);
}